// round 1
// baseline (speedup 1.0000x reference)
#include <cuda_runtime.h>
#include <cstdint>

#define LATENT   128
#define HIDDEN   2048
#define NPARTS   128
#define KCOLS    2048
#define OMEGA_D  (9 * NPARTS)   // 1152
#define TRANZ_D  (3 * NPARTS)   // 384
#define TRANSF_D (12 * NPARTS)  // 1536

// Scratch activations (ping-pong), 2048 x 2048 fp32 each = 16 MB.
__device__ float g_h0[HIDDEN * KCOLS];
__device__ float g_h1[HIDDEN * KCOLS];

// ---------------------------------------------------------------------------
// fp32 SIMT GEMM: C[M,N] = (relu?)(A[M,Kd] @ B[Kd,N]), all row-major.
// BM=BN=128, BK=16, 256 threads, 8x8 accumulators per thread.
// All shapes in this problem are multiples of the tile sizes -> no bounds checks.
// ---------------------------------------------------------------------------
__global__ __launch_bounds__(256) void gemm_relu_kernel(
    const float* __restrict__ A, const float* __restrict__ B,
    float* __restrict__ C, int M, int N, int Kd, int doRelu)
{
    constexpr int BM = 128, BN = 128, BK = 16;
    constexpr int TM = 8, TN = 8;

    __shared__ float As[BK][BM];      // transposed A tile
    __shared__ float Bs[BK][BN];

    const int tid = threadIdx.x;
    const int row0 = blockIdx.y * BM;
    const int col0 = blockIdx.x * BN;

    // A-tile loading coords: float4 along Kd
    const int aRow = tid / (BK / 4);          // 0..63
    const int aCol = (tid % (BK / 4)) * 4;    // 0,4,8,12
    // B-tile loading coords: float4 along N
    const int bRow = tid / (BN / 4);          // 0..7
    const int bCol = (tid % (BN / 4)) * 4;    // 0..124

    const int threadRow = (tid / 16) * TM;    // 0..120
    const int threadCol = (tid % 16) * TN;    // 0..120

    float acc[TM][TN];
#pragma unroll
    for (int i = 0; i < TM; i++)
#pragma unroll
        for (int j = 0; j < TN; j++) acc[i][j] = 0.0f;

    for (int kt = 0; kt < Kd; kt += BK) {
        // load A tile (transposed into As)
#pragma unroll
        for (int r = 0; r < BM; r += 64) {
            float4 v = *(const float4*)&A[(size_t)(row0 + aRow + r) * Kd + kt + aCol];
            As[aCol + 0][aRow + r] = v.x;
            As[aCol + 1][aRow + r] = v.y;
            As[aCol + 2][aRow + r] = v.z;
            As[aCol + 3][aRow + r] = v.w;
        }
        // load B tile
#pragma unroll
        for (int r = 0; r < BK; r += 8) {
            *(float4*)&Bs[bRow + r][bCol] =
                *(const float4*)&B[(size_t)(kt + bRow + r) * N + col0 + bCol];
        }
        __syncthreads();

#pragma unroll
        for (int k = 0; k < BK; k++) {
            float ra[TM], rb[TN];
#pragma unroll
            for (int i = 0; i < TM; i++) ra[i] = As[k][threadRow + i];
#pragma unroll
            for (int j = 0; j < TN; j++) rb[j] = Bs[k][threadCol + j];
#pragma unroll
            for (int i = 0; i < TM; i++)
#pragma unroll
                for (int j = 0; j < TN; j++)
                    acc[i][j] = fmaf(ra[i], rb[j], acc[i][j]);
        }
        __syncthreads();
    }

    // write out (optionally relu), vectorized
#pragma unroll
    for (int i = 0; i < TM; i++) {
        float* crow = &C[(size_t)(row0 + threadRow + i) * N + col0 + threadCol];
#pragma unroll
        for (int j = 0; j < TN; j += 4) {
            float4 v;
            v.x = acc[i][j + 0]; v.y = acc[i][j + 1];
            v.z = acc[i][j + 2]; v.w = acc[i][j + 3];
            if (doRelu) {
                v.x = fmaxf(v.x, 0.0f); v.y = fmaxf(v.y, 0.0f);
                v.z = fmaxf(v.z, 0.0f); v.w = fmaxf(v.w, 0.0f);
            }
            *(float4*)&crow[j] = v;
        }
    }
}

// ---------------------------------------------------------------------------
// 3x3 matrix exponential: inf-norm scaling to <=0.25, 10-term Taylor,
// then repeated squaring. fp32 throughout; agrees with Pade expm to ~1e-6.
// ---------------------------------------------------------------------------
__device__ __forceinline__ void mm3(const float* X, const float* Y, float* Z) {
#pragma unroll
    for (int r = 0; r < 3; r++)
#pragma unroll
        for (int c = 0; c < 3; c++)
            Z[3 * r + c] = fmaf(X[3 * r + 0], Y[c],
                           fmaf(X[3 * r + 1], Y[3 + c],
                                X[3 * r + 2] * Y[6 + c]));
}

__device__ void expm3(const float* A, float* E) {
    float n0 = fabsf(A[0]) + fabsf(A[1]) + fabsf(A[2]);
    float n1 = fabsf(A[3]) + fabsf(A[4]) + fabsf(A[5]);
    float n2 = fabsf(A[6]) + fabsf(A[7]) + fabsf(A[8]);
    float nrm = fmaxf(n0, fmaxf(n1, n2));

    int s = 0;
    if (nrm > 0.25f) {
        s = (int)ceilf(log2f(nrm * 4.0f));
        if (s < 0) s = 0;
    }
    float sc = exp2f((float)(-s));

    float B[9], T[9];
#pragma unroll
    for (int i = 0; i < 9; i++) B[i] = A[i] * sc;
#pragma unroll
    for (int i = 0; i < 9; i++) {
        T[i] = B[i];
        E[i] = ((i == 0) | (i == 4) | (i == 8)) ? 1.0f + B[i] : B[i];
    }
#pragma unroll
    for (int j = 2; j <= 10; j++) {
        float Tn[9];
        mm3(T, B, Tn);
        float inv = 1.0f / (float)j;
#pragma unroll
        for (int i = 0; i < 9; i++) {
            Tn[i] *= inv;
            E[i] += Tn[i];
            T[i] = Tn[i];
        }
    }
    for (int q = 0; q < s; q++) {
        float S[9];
        mm3(E, E, S);
#pragma unroll
        for (int i = 0; i < 9; i++) E[i] = S[i];
    }
}

// One thread per (part p, column k). Reads omega column-slice, writes
// rotations + full transf block (rot rows 0..8, translation rows 9..11).
__global__ __launch_bounds__(256) void expm_assemble_kernel(
    const float* __restrict__ omega,   // (9n, K)
    const float* __restrict__ trans,   // (3n, K)
    float* __restrict__ rot_out,       // (9n, K)
    float* __restrict__ transf_out)    // (12n, K)
{
    const int k = blockIdx.x * blockDim.x + threadIdx.x;  // 0..K-1
    const int p = blockIdx.y;                             // 0..n-1

    float Amat[9];
#pragma unroll
    for (int j = 0; j < 9; j++)
        Amat[j] = omega[(size_t)(9 * p + j) * KCOLS + k];

    float E[9];
    expm3(Amat, E);

#pragma unroll
    for (int j = 0; j < 9; j++) {
        rot_out[(size_t)(9 * p + j) * KCOLS + k]     = E[j];
        transf_out[(size_t)(12 * p + j) * KCOLS + k] = E[j];
    }
#pragma unroll
    for (int c = 0; c < 3; c++)
        transf_out[(size_t)(12 * p + 9 + c) * KCOLS + k] =
            trans[(size_t)(3 * p + c) * KCOLS + k];
}

// ---------------------------------------------------------------------------
// kernel_launch
// Inputs (metadata order): x_init, Wo0, Wo1, Wo2, Wo3, Wt0, Wt1, Wt2, Wt3
// Output: concat(omega (1152,K) | transf (1536,K) | rotations (1152,K) |
//                translations (384,K)), fp32.
// ---------------------------------------------------------------------------
extern "C" void kernel_launch(void* const* d_in, const int* in_sizes, int n_in,
                              void* d_out, int out_size)
{
    const float* x   = (const float*)d_in[0];
    const float* Wo0 = (const float*)d_in[1];
    const float* Wo1 = (const float*)d_in[2];
    const float* Wo2 = (const float*)d_in[3];
    const float* Wo3 = (const float*)d_in[4];
    const float* Wt0 = (const float*)d_in[5];
    const float* Wt1 = (const float*)d_in[6];
    const float* Wt2 = (const float*)d_in[7];
    const float* Wt3 = (const float*)d_in[8];

    float* out    = (float*)d_out;
    float* omega  = out;
    float* transf = omega  + (size_t)OMEGA_D  * KCOLS;
    float* rot    = transf + (size_t)TRANSF_D * KCOLS;
    float* trans  = rot    + (size_t)OMEGA_D  * KCOLS;

    float* h0 = nullptr;
    float* h1 = nullptr;
    cudaGetSymbolAddress((void**)&h0, g_h0);
    cudaGetSymbolAddress((void**)&h1, g_h1);

    dim3 threads(256);
    auto launch_gemm = [&](const float* A, const float* B, float* C,
                           int M, int Kd, int relu) {
        dim3 grid(KCOLS / 128, M / 128);
        gemm_relu_kernel<<<grid, threads>>>(A, B, C, M, KCOLS, Kd, relu);
    };

    // omega MLP
    launch_gemm(Wo0, x,  h0, HIDDEN,  LATENT, 1);
    launch_gemm(Wo1, h0, h1, HIDDEN,  HIDDEN, 1);
    launch_gemm(Wo2, h1, h0, HIDDEN,  HIDDEN, 1);
    launch_gemm(Wo3, h0, omega, OMEGA_D, HIDDEN, 0);

    // translation MLP
    launch_gemm(Wt0, x,  h0, HIDDEN,  LATENT, 1);
    launch_gemm(Wt1, h0, h1, HIDDEN,  HIDDEN, 1);
    launch_gemm(Wt2, h1, h0, HIDDEN,  HIDDEN, 1);
    launch_gemm(Wt3, h0, trans, TRANZ_D, HIDDEN, 0);

    // expm + transf assembly
    dim3 ge(KCOLS / 256, NPARTS);
    expm_assemble_kernel<<<ge, 256>>>(omega, trans, rot, transf);
}

// round 3
// speedup vs baseline: 2.2234x; 2.2234x over previous
#include <cuda_runtime.h>
#include <cuda_bf16.h>
#include <cstdint>

#define LATENT   128
#define HIDDEN   2048
#define NPARTS   128
#define KCOLS    2048
#define OMEGA_D  1152
#define TRANZ_D  384
#define TRANSF_D 1536

// ---------------------------------------------------------------------------
// Scratch (__device__ globals; allocation-guard-safe)
// ---------------------------------------------------------------------------
#define W_TOTAL (2048*128 + 2048*2048 + 2048*2048 + 1152*2048 + \
                 2048*128 + 2048*2048 + 2048*2048 + 384*2048)

__device__ __nv_bfloat16 g_w_hi[W_TOTAL];
__device__ __nv_bfloat16 g_w_lo[W_TOTAL];
__device__ __nv_bfloat16 g_act_hi[2][HIDDEN * KCOLS];
__device__ __nv_bfloat16 g_act_lo[2][HIDDEN * KCOLS];
__device__ __nv_bfloat16 g_xt_hi[KCOLS * LATENT];
__device__ __nv_bfloat16 g_xt_lo[KCOLS * LATENT];
__device__ float g_omega_t[(size_t)KCOLS * OMEGA_D];
__device__ float g_trans_t[(size_t)KCOLS * TRANZ_D];

// ---------------------------------------------------------------------------
// PTX helpers (base ISA only: ldmatrix / mma.sync / cp.async)
// ---------------------------------------------------------------------------
__device__ __forceinline__ uint32_t smem_u32(const void* p) {
    uint32_t a;
    asm("{ .reg .u64 t; cvta.to.shared.u64 t, %1; cvt.u32.u64 %0, t; }" : "=r"(a) : "l"(p));
    return a;
}
__device__ __forceinline__ void cp16(uint32_t s, const void* g) {
    asm volatile("cp.async.cg.shared.global [%0], [%1], 16;" :: "r"(s), "l"(g) : "memory");
}
#define CP_COMMIT() asm volatile("cp.async.commit_group;" ::: "memory")

__device__ __forceinline__ void ldsm_x4(uint32_t addr, uint32_t* r) {
    asm volatile("ldmatrix.sync.aligned.m8n8.x4.shared.b16 {%0,%1,%2,%3}, [%4];"
                 : "=r"(r[0]), "=r"(r[1]), "=r"(r[2]), "=r"(r[3]) : "r"(addr));
}
__device__ __forceinline__ void mma_bf16(float* c, const uint32_t* a,
                                         uint32_t b0, uint32_t b1) {
    asm volatile(
        "mma.sync.aligned.m16n8k16.row.col.f32.bf16.bf16.f32 "
        "{%0,%1,%2,%3}, {%4,%5,%6,%7}, {%8,%9}, {%0,%1,%2,%3};"
        : "+f"(c[0]), "+f"(c[1]), "+f"(c[2]), "+f"(c[3])
        : "r"(a[0]), "r"(a[1]), "r"(a[2]), "r"(a[3]), "r"(b0), "r"(b1));
}

// ---------------------------------------------------------------------------
// Split kernels: fp32 -> (hi, lo) bf16
// ---------------------------------------------------------------------------
__global__ __launch_bounds__(256) void split_kernel(
    const float* __restrict__ in, __nv_bfloat16* __restrict__ hi,
    __nv_bfloat16* __restrict__ lo, int n)
{
    int i = blockIdx.x * 256 + threadIdx.x;
    if (i >= n) return;
    float v = in[i];
    __nv_bfloat16 h = __float2bfloat16(v);
    hi[i] = h;
    lo[i] = __float2bfloat16(v - __bfloat162float(h));
}

__global__ __launch_bounds__(256) void split_xT_kernel(
    const float* __restrict__ x, __nv_bfloat16* __restrict__ hi,
    __nv_bfloat16* __restrict__ lo)
{
    int i = blockIdx.x * 256 + threadIdx.x;  // i = n*LATENT + f
    int f = i & (LATENT - 1);
    int n = i >> 7;
    float v = x[(size_t)f * KCOLS + n];
    __nv_bfloat16 h = __float2bfloat16(v);
    hi[i] = h;
    lo[i] = __float2bfloat16(v - __bfloat162float(h));
}

// ---------------------------------------------------------------------------
// HMMA split-bf16 GEMM.
//   Logical: C[M, KCOLS] = A[M, Kd] @ Bt[KCOLS, Kd]^T
//   A = weights (row-major, K-contig), Bt = transposed activations (K-contig).
//   Output written TRANSPOSED [n][M]. mode 0: relu + hi/lo split; 1: fp32 raw.
// CTA tile 128x128x32, 512 threads, warp tile 32x32, 3-stage cp.async.
// ---------------------------------------------------------------------------
#define BM 128
#define BN 128
#define BK 32
#define GT 512
#define PITCH 80                 // bytes per SMEM row (64 data + 16 pad)
#define TILE_B (128 * PITCH)     // 10240 bytes per operand tile
#define STAGE_B (4 * TILE_B)     // Ah, Al, Bh, Bl
#define NSTAGE 3
#define GEMM_SMEM (NSTAGE * STAGE_B)   // 122880
#define OFF_AH 0
#define OFF_AL TILE_B
#define OFF_BH (2 * TILE_B)
#define OFF_BL (3 * TILE_B)

__device__ __forceinline__ void load_stage(
    const __nv_bfloat16* __restrict__ Ah, const __nv_bfloat16* __restrict__ Al,
    const __nv_bfloat16* __restrict__ Bh, const __nv_bfloat16* __restrict__ Bl,
    int Kd, int m0, int n0, int kk, uint32_t stage_sb, int tid)
{
    const int rr = tid >> 2;          // row 0..127
    const int cb = (tid & 3) * 16;    // 16B chunk in 64B row
    const size_t goff = (size_t)rr * Kd + kk;
    uint32_t sa = stage_sb + rr * PITCH + cb;
    cp16(sa + OFF_AH, (const char*)(Ah + (size_t)m0 * Kd + goff) + cb);
    cp16(sa + OFF_AL, (const char*)(Al + (size_t)m0 * Kd + goff) + cb);
    cp16(sa + OFF_BH, (const char*)(Bh + (size_t)n0 * Kd + goff) + cb);
    cp16(sa + OFF_BL, (const char*)(Bl + (size_t)n0 * Kd + goff) + cb);
}

__global__ __launch_bounds__(GT, 1) void gemm_hmma_kernel(
    const __nv_bfloat16* __restrict__ A_hi, const __nv_bfloat16* __restrict__ A_lo,
    const __nv_bfloat16* __restrict__ B_hi, const __nv_bfloat16* __restrict__ B_lo,
    __nv_bfloat16* __restrict__ out_hi, __nv_bfloat16* __restrict__ out_lo,
    float* __restrict__ out_f32, int M, int Kd, int mode)
{
    extern __shared__ __align__(128) char smem[];
    const uint32_t sb = smem_u32(smem);
    const int tid = threadIdx.x;
    const int lane = tid & 31;
    const int wid = tid >> 5;                // 0..15
    const int warp_m0 = (wid & 3) * 32;
    const int warp_n0 = (wid >> 2) * 32;
    const int m0 = blockIdx.y * BM;
    const int n0 = blockIdx.x * BN;
    const int KT = Kd / BK;

    // ldmatrix per-thread address components
    const int a_row = (lane & 7) + ((lane >> 3) & 1) * 8;  // within m16 tile
    const int a_kb  = (lane >> 4) * 16;                    // k-half byte offset
    const int b_row = (lane & 7) + (lane >> 4) * 8;        // within n16 group
    const int b_kb  = ((lane >> 3) & 1) * 16;

    float acc[2][4][4];
#pragma unroll
    for (int mt = 0; mt < 2; mt++)
#pragma unroll
        for (int nt = 0; nt < 4; nt++)
#pragma unroll
            for (int i = 0; i < 4; i++) acc[mt][nt][i] = 0.0f;

    // prologue: stages 0 and 1
    load_stage(A_hi, A_lo, B_hi, B_lo, Kd, m0, n0, 0, sb, tid);
    CP_COMMIT();
    load_stage(A_hi, A_lo, B_hi, B_lo, Kd, m0, n0, BK, sb + STAGE_B, tid);
    CP_COMMIT();

    for (int kt = 0; kt < KT; kt++) {
        if (kt + 1 < KT) asm volatile("cp.async.wait_group 1;" ::: "memory");
        else             asm volatile("cp.async.wait_group 0;" ::: "memory");
        __syncthreads();

        const uint32_t st = sb + (kt % NSTAGE) * STAGE_B;
#pragma unroll
        for (int ks = 0; ks < 2; ks++) {
            const int kb = ks * 32;  // 16 bf16 = 32B
            uint32_t ah[2][4], al[2][4], bh[2][4], bl[2][4];
#pragma unroll
            for (int mt = 0; mt < 2; mt++) {
                uint32_t ra = st + (warp_m0 + mt * 16 + a_row) * PITCH + kb + a_kb;
                ldsm_x4(ra + OFF_AH, ah[mt]);
                ldsm_x4(ra + OFF_AL, al[mt]);
            }
#pragma unroll
            for (int g = 0; g < 2; g++) {
                uint32_t rb = st + (warp_n0 + g * 16 + b_row) * PITCH + kb + b_kb;
                ldsm_x4(rb + OFF_BH, bh[g]);
                ldsm_x4(rb + OFF_BL, bl[g]);
            }
#pragma unroll
            for (int mt = 0; mt < 2; mt++)
#pragma unroll
                for (int nt = 0; nt < 4; nt++) {
                    const int g = nt >> 1, p = (nt & 1) * 2;
                    mma_bf16(acc[mt][nt], ah[mt], bh[g][p], bh[g][p + 1]);
                    mma_bf16(acc[mt][nt], ah[mt], bl[g][p], bl[g][p + 1]);
                    mma_bf16(acc[mt][nt], al[mt], bh[g][p], bh[g][p + 1]);
                }
        }

        if (kt + 2 < KT) {
            load_stage(A_hi, A_lo, B_hi, B_lo, Kd, m0, n0, (kt + 2) * BK,
                       sb + ((kt + 2) % NSTAGE) * STAGE_B, tid);
        }
        CP_COMMIT();   // keep group count in lockstep even when empty
    }

    // ---------------- epilogue: transpose via SMEM ----------------
    __syncthreads();
    float* sC = (float*)smem;  // [128 n][132 m]
    const int crow = lane >> 2, ccol = (lane & 3) * 2;
#pragma unroll
    for (int mt = 0; mt < 2; mt++)
#pragma unroll
        for (int nt = 0; nt < 4; nt++) {
            const int m_ = warp_m0 + mt * 16 + crow;
            const int n_ = warp_n0 + nt * 8 + ccol;
            const float* c = acc[mt][nt];
            sC[(size_t)n_ * 132 + m_]           = c[0];
            sC[(size_t)(n_ + 1) * 132 + m_]     = c[1];
            sC[(size_t)n_ * 132 + m_ + 8]       = c[2];
            sC[(size_t)(n_ + 1) * 132 + m_ + 8] = c[3];
        }
    __syncthreads();

    const int r  = tid >> 2;          // n row 0..127
    const int mq = (tid & 3) * 32;    // m quarter
    const size_t base = (size_t)(n0 + r) * M + m0 + mq;
    if (mode == 0) {
#pragma unroll
        for (int j0 = 0; j0 < 32; j0 += 8) {
            __align__(16) __nv_bfloat16 h8[8], l8[8];
#pragma unroll
            for (int j = 0; j < 8; j++) {
                float v = fmaxf(sC[(size_t)r * 132 + mq + j0 + j], 0.0f);
                __nv_bfloat16 h = __float2bfloat16(v);
                h8[j] = h;
                l8[j] = __float2bfloat16(v - __bfloat162float(h));
            }
            *(uint4*)(out_hi + base + j0) = *(const uint4*)h8;
            *(uint4*)(out_lo + base + j0) = *(const uint4*)l8;
        }
    } else {
#pragma unroll
        for (int j0 = 0; j0 < 32; j0 += 4) {
            float4 v;
            v.x = sC[(size_t)r * 132 + mq + j0 + 0];
            v.y = sC[(size_t)r * 132 + mq + j0 + 1];
            v.z = sC[(size_t)r * 132 + mq + j0 + 2];
            v.w = sC[(size_t)r * 132 + mq + j0 + 3];
            *(float4*)(out_f32 + base + j0) = v;
        }
    }
}

// ---------------------------------------------------------------------------
// expm (3x3) + output assembly (reads transposed scratch, coalesced writes)
// ---------------------------------------------------------------------------
__device__ __forceinline__ void mm3(const float* X, const float* Y, float* Z) {
#pragma unroll
    for (int r = 0; r < 3; r++)
#pragma unroll
        for (int c = 0; c < 3; c++)
            Z[3 * r + c] = fmaf(X[3 * r + 0], Y[c],
                           fmaf(X[3 * r + 1], Y[3 + c], X[3 * r + 2] * Y[6 + c]));
}

__device__ void expm3(const float* A, float* E) {
    float n0 = fabsf(A[0]) + fabsf(A[1]) + fabsf(A[2]);
    float n1 = fabsf(A[3]) + fabsf(A[4]) + fabsf(A[5]);
    float n2 = fabsf(A[6]) + fabsf(A[7]) + fabsf(A[8]);
    float nrm = fmaxf(n0, fmaxf(n1, n2));
    int s = 0;
    if (nrm > 0.25f) {
        s = (int)ceilf(log2f(nrm * 4.0f));
        if (s < 0) s = 0;
    }
    float sc = exp2f((float)(-s));
    float B[9], T[9];
#pragma unroll
    for (int i = 0; i < 9; i++) B[i] = A[i] * sc;
#pragma unroll
    for (int i = 0; i < 9; i++) {
        T[i] = B[i];
        E[i] = ((i == 0) | (i == 4) | (i == 8)) ? 1.0f + B[i] : B[i];
    }
#pragma unroll
    for (int j = 2; j <= 10; j++) {
        float Tn[9];
        mm3(T, B, Tn);
        float inv = 1.0f / (float)j;
#pragma unroll
        for (int i = 0; i < 9; i++) { Tn[i] *= inv; E[i] += Tn[i]; T[i] = Tn[i]; }
    }
    for (int q = 0; q < s; q++) {
        float S[9];
        mm3(E, E, S);
#pragma unroll
        for (int i = 0; i < 9; i++) E[i] = S[i];
    }
}

__global__ __launch_bounds__(256) void expm_assemble_kernel(
    const float* __restrict__ omega_t,  // (K, 9n)
    const float* __restrict__ trans_t,  // (K, 3n)
    float* __restrict__ omega_out,      // (9n, K)
    float* __restrict__ transf,         // (12n, K)
    float* __restrict__ rot,            // (9n, K)
    float* __restrict__ trans_out)      // (3n, K)
{
    const int n = blockIdx.x * 256 + threadIdx.x;
    const int p = blockIdx.y;

    float Am[9];
    const float* src = omega_t + (size_t)n * OMEGA_D + 9 * p;
#pragma unroll
    for (int j = 0; j < 9; j++) Am[j] = __ldg(src + j);

    float E[9];
    expm3(Am, E);

#pragma unroll
    for (int j = 0; j < 9; j++) {
        omega_out[(size_t)(9 * p + j) * KCOLS + n] = Am[j];
        rot[(size_t)(9 * p + j) * KCOLS + n]       = E[j];
        transf[(size_t)(12 * p + j) * KCOLS + n]   = E[j];
    }
    const float* tsrc = trans_t + (size_t)n * TRANZ_D + 3 * p;
#pragma unroll
    for (int c = 0; c < 3; c++) {
        float tv = __ldg(tsrc + c);
        trans_out[(size_t)(3 * p + c) * KCOLS + n]   = tv;
        transf[(size_t)(12 * p + 9 + c) * KCOLS + n] = tv;
    }
}

// ---------------------------------------------------------------------------
// kernel_launch
// ---------------------------------------------------------------------------
extern "C" void kernel_launch(void* const* d_in, const int* in_sizes, int n_in,
                              void* d_out, int out_size)
{
    const float* x = (const float*)d_in[0];
    const float* W[8];
    for (int i = 0; i < 8; i++) W[i] = (const float*)d_in[1 + i];

    const int wsz[8] = {2048 * 128, 2048 * 2048, 2048 * 2048, 1152 * 2048,
                        2048 * 128, 2048 * 2048, 2048 * 2048, 384 * 2048};
    size_t woff[8];
    size_t acc = 0;
    for (int i = 0; i < 8; i++) { woff[i] = acc; acc += wsz[i]; }

    float* out    = (float*)d_out;
    float* omega  = out;
    float* transf = omega  + (size_t)OMEGA_D  * KCOLS;
    float* rot    = transf + (size_t)TRANSF_D * KCOLS;
    float* trans  = rot    + (size_t)OMEGA_D  * KCOLS;

    __nv_bfloat16 *w_hi, *w_lo, *xt_hi, *xt_lo;
    __nv_bfloat16 *a_hi[2], *a_lo[2];
    float *omega_t, *trans_t;
    cudaGetSymbolAddress((void**)&w_hi, g_w_hi);
    cudaGetSymbolAddress((void**)&w_lo, g_w_lo);
    cudaGetSymbolAddress((void**)&xt_hi, g_xt_hi);
    cudaGetSymbolAddress((void**)&xt_lo, g_xt_lo);
    {
        __nv_bfloat16* p;
        cudaGetSymbolAddress((void**)&p, g_act_hi);
        a_hi[0] = p; a_hi[1] = p + (size_t)HIDDEN * KCOLS;
        cudaGetSymbolAddress((void**)&p, g_act_lo);
        a_lo[0] = p; a_lo[1] = p + (size_t)HIDDEN * KCOLS;
    }
    cudaGetSymbolAddress((void**)&omega_t, g_omega_t);
    cudaGetSymbolAddress((void**)&trans_t, g_trans_t);

    cudaFuncSetAttribute(gemm_hmma_kernel,
                         cudaFuncAttributeMaxDynamicSharedMemorySize, GEMM_SMEM);

    // 1) split weights + x
    for (int i = 0; i < 8; i++)
        split_kernel<<<(wsz[i] + 255) / 256, 256>>>(W[i], w_hi + woff[i],
                                                    w_lo + woff[i], wsz[i]);
    split_xT_kernel<<<(KCOLS * LATENT) / 256, 256>>>(x, xt_hi, xt_lo);

    // 2) GEMM chains (activations transposed throughout)
    auto gemm = [&](int wi, const __nv_bfloat16* bh, const __nv_bfloat16* bl,
                    __nv_bfloat16* oh, __nv_bfloat16* ol, float* of,
                    int M, int Kd, int mode) {
        dim3 grid(KCOLS / BN, M / BM);
        gemm_hmma_kernel<<<grid, GT, GEMM_SMEM>>>(
            w_hi + woff[wi], w_lo + woff[wi], bh, bl, oh, ol, of, M, Kd, mode);
    };

    // omega branch
    gemm(0, xt_hi,   xt_lo,   a_hi[0], a_lo[0], nullptr, HIDDEN,  LATENT, 0);
    gemm(1, a_hi[0], a_lo[0], a_hi[1], a_lo[1], nullptr, HIDDEN,  HIDDEN, 0);
    gemm(2, a_hi[1], a_lo[1], a_hi[0], a_lo[0], nullptr, HIDDEN,  HIDDEN, 0);
    gemm(3, a_hi[0], a_lo[0], nullptr, nullptr, omega_t, OMEGA_D, HIDDEN, 1);
    // translation branch
    gemm(4, xt_hi,   xt_lo,   a_hi[0], a_lo[0], nullptr, HIDDEN,  LATENT, 0);
    gemm(5, a_hi[0], a_lo[0], a_hi[1], a_lo[1], nullptr, HIDDEN,  HIDDEN, 0);
    gemm(6, a_hi[1], a_lo[1], a_hi[0], a_lo[0], nullptr, HIDDEN,  HIDDEN, 0);
    gemm(7, a_hi[0], a_lo[0], nullptr, nullptr, trans_t, TRANZ_D, HIDDEN, 1);

    // 3) expm + assembly
    dim3 ge(KCOLS / 256, NPARTS);
    expm_assemble_kernel<<<ge, 256>>>(omega_t, trans_t, omega, transf, rot, trans);
}

// round 4
// speedup vs baseline: 2.3979x; 1.0785x over previous
#include <cuda_runtime.h>
#include <cuda_bf16.h>
#include <cstdint>

#define LATENT   128
#define HIDDEN   2048
#define NPARTS   128
#define KCOLS    2048
#define OMEGA_D  1152
#define TRANZ_D  384
#define TRANSF_D 1536

// ---------------------------------------------------------------------------
// Scratch (__device__ globals; allocation-guard-safe)
// ---------------------------------------------------------------------------
#define W_TOTAL (2048*128 + 2048*2048 + 2048*2048 + 1152*2048 + \
                 2048*128 + 2048*2048 + 2048*2048 + 384*2048)

__device__ __nv_bfloat16 g_w_hi[W_TOTAL];
__device__ __nv_bfloat16 g_w_lo[W_TOTAL];
__device__ __nv_bfloat16 g_act_hi[2][HIDDEN * KCOLS];
__device__ __nv_bfloat16 g_act_lo[2][HIDDEN * KCOLS];
__device__ __nv_bfloat16 g_xt_hi[KCOLS * LATENT];
__device__ __nv_bfloat16 g_xt_lo[KCOLS * LATENT];
__device__ float g_omega_t[(size_t)KCOLS * OMEGA_D];
__device__ float g_trans_t[(size_t)KCOLS * TRANZ_D];

// ---------------------------------------------------------------------------
// PTX helpers (base ISA: ldmatrix / mma.sync / cp.async)
// ---------------------------------------------------------------------------
__device__ __forceinline__ uint32_t smem_u32(const void* p) {
    uint32_t a;
    asm("{ .reg .u64 t; cvta.to.shared.u64 t, %1; cvt.u32.u64 %0, t; }" : "=r"(a) : "l"(p));
    return a;
}
__device__ __forceinline__ void cp16(uint32_t s, const void* g) {
    asm volatile("cp.async.cg.shared.global [%0], [%1], 16;" :: "r"(s), "l"(g) : "memory");
}
#define CP_COMMIT() asm volatile("cp.async.commit_group;" ::: "memory")

__device__ __forceinline__ void ldsm_x4(uint32_t addr, uint32_t* r) {
    asm volatile("ldmatrix.sync.aligned.m8n8.x4.shared.b16 {%0,%1,%2,%3}, [%4];"
                 : "=r"(r[0]), "=r"(r[1]), "=r"(r[2]), "=r"(r[3]) : "r"(addr));
}
__device__ __forceinline__ void mma_bf16(float* c, const uint32_t* a,
                                         uint32_t b0, uint32_t b1) {
    asm volatile(
        "mma.sync.aligned.m16n8k16.row.col.f32.bf16.bf16.f32 "
        "{%0,%1,%2,%3}, {%4,%5,%6,%7}, {%8,%9}, {%0,%1,%2,%3};"
        : "+f"(c[0]), "+f"(c[1]), "+f"(c[2]), "+f"(c[3])
        : "r"(a[0]), "r"(a[1]), "r"(a[2]), "r"(a[3]), "r"(b0), "r"(b1));
}

// ---------------------------------------------------------------------------
// Split kernels: fp32 -> (hi, lo) bf16   (vectorized: 4 elems / thread)
// ---------------------------------------------------------------------------
__global__ __launch_bounds__(256) void split4_kernel(
    const float* __restrict__ in, __nv_bfloat16* __restrict__ hi,
    __nv_bfloat16* __restrict__ lo, int n4)
{
    int i = blockIdx.x * 256 + threadIdx.x;
    if (i >= n4) return;
    float4 v = ((const float4*)in)[i];
    __nv_bfloat16 h[4], l[4];
    float f[4] = {v.x, v.y, v.z, v.w};
#pragma unroll
    for (int j = 0; j < 4; j++) {
        h[j] = __float2bfloat16(f[j]);
        l[j] = __float2bfloat16(f[j] - __bfloat162float(h[j]));
    }
    ((uint2*)hi)[i] = *(const uint2*)h;
    ((uint2*)lo)[i] = *(const uint2*)l;
}

__global__ __launch_bounds__(256) void split_xT_kernel(
    const float* __restrict__ x, __nv_bfloat16* __restrict__ hi,
    __nv_bfloat16* __restrict__ lo)
{
    int i = blockIdx.x * 256 + threadIdx.x;  // i = n*LATENT + f
    int f = i & (LATENT - 1);
    int n = i >> 7;
    float v = x[(size_t)f * KCOLS + n];
    __nv_bfloat16 h = __float2bfloat16(v);
    hi[i] = h;
    lo[i] = __float2bfloat16(v - __bfloat162float(h));
}

// ---------------------------------------------------------------------------
// HMMA split-bf16 GEMM.
//   Logical: C[M, KCOLS] = A[M, Kd] @ Bt[KCOLS, Kd]^T
//   Output TRANSPOSED [n][M]. mode 0: relu + hi/lo split; 1: fp32 raw.
// CTA tile 128x128x32, 256 threads, warp tile 64x32 (2x4 warp grid),
// 3-stage cp.async pipeline, single barrier per K-step.
// ---------------------------------------------------------------------------
#define BM 128
#define BN 128
#define BK 32
#define GT 256
#define PITCH 80                 // bytes per SMEM row (64 data + 16 pad)
#define TILE_B (128 * PITCH)     // 10240 bytes per operand tile
#define STAGE_B (4 * TILE_B)     // Ah, Al, Bh, Bl
#define NSTAGE 3
#define GEMM_SMEM (NSTAGE * STAGE_B)   // 122880
#define OFF_AH 0
#define OFF_AL TILE_B
#define OFF_BH (2 * TILE_B)
#define OFF_BL (3 * TILE_B)

__device__ __forceinline__ void load_stage(
    const __nv_bfloat16* __restrict__ Ah, const __nv_bfloat16* __restrict__ Al,
    const __nv_bfloat16* __restrict__ Bh, const __nv_bfloat16* __restrict__ Bl,
    int Kd, int m0, int n0, int kk, uint32_t stage_sb, int tid)
{
    const int rr = tid >> 2;          // 0..63
    const int cb = (tid & 3) * 16;    // 16B chunk in 64B row
#pragma unroll
    for (int h = 0; h < 2; h++) {
        const int row = rr + h * 64;
        const size_t goff = (size_t)row * Kd + kk;
        const uint32_t sa = stage_sb + row * PITCH + cb;
        cp16(sa + OFF_AH, (const char*)(Ah + (size_t)m0 * Kd + goff) + cb);
        cp16(sa + OFF_AL, (const char*)(Al + (size_t)m0 * Kd + goff) + cb);
        cp16(sa + OFF_BH, (const char*)(Bh + (size_t)n0 * Kd + goff) + cb);
        cp16(sa + OFF_BL, (const char*)(Bl + (size_t)n0 * Kd + goff) + cb);
    }
}

__global__ __launch_bounds__(GT, 1) void gemm_hmma_kernel(
    const __nv_bfloat16* __restrict__ A_hi, const __nv_bfloat16* __restrict__ A_lo,
    const __nv_bfloat16* __restrict__ B_hi, const __nv_bfloat16* __restrict__ B_lo,
    __nv_bfloat16* __restrict__ out_hi, __nv_bfloat16* __restrict__ out_lo,
    float* __restrict__ out_f32, int M, int Kd, int mode)
{
    extern __shared__ __align__(128) char smem[];
    const uint32_t sb = smem_u32(smem);
    const int tid = threadIdx.x;
    const int lane = tid & 31;
    const int wid = tid >> 5;                 // 0..7
    const int warp_m0 = (wid & 1) * 64;       // 2 m-warps
    const int warp_n0 = (wid >> 1) * 32;      // 4 n-warps
    const int m0 = blockIdx.y * BM;
    const int n0 = blockIdx.x * BN;
    const int KT = Kd / BK;

    // ldmatrix per-thread address components
    const int a_row = (lane & 7) + ((lane >> 3) & 1) * 8;
    const int a_kb  = (lane >> 4) * 16;
    const int b_row = (lane & 7) + (lane >> 4) * 8;
    const int b_kb  = ((lane >> 3) & 1) * 16;

    float acc[4][4][4];
#pragma unroll
    for (int mt = 0; mt < 4; mt++)
#pragma unroll
        for (int nt = 0; nt < 4; nt++)
#pragma unroll
            for (int i = 0; i < 4; i++) acc[mt][nt][i] = 0.0f;

    // prologue: stages 0 and 1
    load_stage(A_hi, A_lo, B_hi, B_lo, Kd, m0, n0, 0, sb, tid);
    CP_COMMIT();
    load_stage(A_hi, A_lo, B_hi, B_lo, Kd, m0, n0, BK, sb + STAGE_B, tid);
    CP_COMMIT();

    for (int kt = 0; kt < KT; kt++) {
        asm volatile("cp.async.wait_group 1;" ::: "memory");
        __syncthreads();

        // prefetch kt+2 into the slot consumed at kt-1 (safe after the sync)
        if (kt + 2 < KT) {
            load_stage(A_hi, A_lo, B_hi, B_lo, Kd, m0, n0, (kt + 2) * BK,
                       sb + ((kt + 2) % NSTAGE) * STAGE_B, tid);
        }
        CP_COMMIT();   // commit every iteration to keep group count in lockstep

        const uint32_t st = sb + (kt % NSTAGE) * STAGE_B;
#pragma unroll
        for (int ks = 0; ks < 2; ks++) {
            const int kb = ks * 32;  // 16 bf16 = 32B
            uint32_t ah[4][4], al[4][4], bh[2][4], bl[2][4];
#pragma unroll
            for (int mt = 0; mt < 4; mt++) {
                uint32_t ra = st + (warp_m0 + mt * 16 + a_row) * PITCH + kb + a_kb;
                ldsm_x4(ra + OFF_AH, ah[mt]);
                ldsm_x4(ra + OFF_AL, al[mt]);
            }
#pragma unroll
            for (int g = 0; g < 2; g++) {
                uint32_t rb = st + (warp_n0 + g * 16 + b_row) * PITCH + kb + b_kb;
                ldsm_x4(rb + OFF_BH, bh[g]);
                ldsm_x4(rb + OFF_BL, bl[g]);
            }
#pragma unroll
            for (int mt = 0; mt < 4; mt++)
#pragma unroll
                for (int nt = 0; nt < 4; nt++) {
                    const int g = nt >> 1, p = (nt & 1) * 2;
                    mma_bf16(acc[mt][nt], ah[mt], bh[g][p], bh[g][p + 1]);
                    mma_bf16(acc[mt][nt], ah[mt], bl[g][p], bl[g][p + 1]);
                    mma_bf16(acc[mt][nt], al[mt], bh[g][p], bh[g][p + 1]);
                }
        }
    }

    // ---------------- epilogue: transpose via SMEM ----------------
    __syncthreads();
    float* sC = (float*)smem;  // [128 n][132 m]
    const int crow = lane >> 2, ccol = (lane & 3) * 2;
#pragma unroll
    for (int mt = 0; mt < 4; mt++)
#pragma unroll
        for (int nt = 0; nt < 4; nt++) {
            const int m_ = warp_m0 + mt * 16 + crow;
            const int n_ = warp_n0 + nt * 8 + ccol;
            const float* c = acc[mt][nt];
            sC[(size_t)n_ * 132 + m_]           = c[0];
            sC[(size_t)(n_ + 1) * 132 + m_]     = c[1];
            sC[(size_t)n_ * 132 + m_ + 8]       = c[2];
            sC[(size_t)(n_ + 1) * 132 + m_ + 8] = c[3];
        }
    __syncthreads();

    const int r  = tid >> 1;          // n row 0..127
    const int mh = (tid & 1) * 64;    // m half
    const size_t base = (size_t)(n0 + r) * M + m0 + mh;
    const float* srow = &sC[(size_t)r * 132 + mh];
    if (mode == 0) {
#pragma unroll
        for (int j0 = 0; j0 < 64; j0 += 8) {
            __align__(16) __nv_bfloat16 h8[8], l8[8];
#pragma unroll
            for (int j = 0; j < 8; j++) {
                float v = fmaxf(srow[j0 + j], 0.0f);
                __nv_bfloat16 h = __float2bfloat16(v);
                h8[j] = h;
                l8[j] = __float2bfloat16(v - __bfloat162float(h));
            }
            *(uint4*)(out_hi + base + j0) = *(const uint4*)h8;
            *(uint4*)(out_lo + base + j0) = *(const uint4*)l8;
        }
    } else {
#pragma unroll
        for (int j0 = 0; j0 < 64; j0 += 4) {
            float4 v;
            v.x = srow[j0 + 0]; v.y = srow[j0 + 1];
            v.z = srow[j0 + 2]; v.w = srow[j0 + 3];
            *(float4*)(out_f32 + base + j0) = v;
        }
    }
}

// ---------------------------------------------------------------------------
// expm (3x3) + output assembly (reads transposed scratch, coalesced writes)
// ---------------------------------------------------------------------------
__device__ __forceinline__ void mm3(const float* X, const float* Y, float* Z) {
#pragma unroll
    for (int r = 0; r < 3; r++)
#pragma unroll
        for (int c = 0; c < 3; c++)
            Z[3 * r + c] = fmaf(X[3 * r + 0], Y[c],
                           fmaf(X[3 * r + 1], Y[3 + c], X[3 * r + 2] * Y[6 + c]));
}

__device__ void expm3(const float* A, float* E) {
    float n0 = fabsf(A[0]) + fabsf(A[1]) + fabsf(A[2]);
    float n1 = fabsf(A[3]) + fabsf(A[4]) + fabsf(A[5]);
    float n2 = fabsf(A[6]) + fabsf(A[7]) + fabsf(A[8]);
    float nrm = fmaxf(n0, fmaxf(n1, n2));
    int s = 0;
    if (nrm > 0.25f) {
        s = (int)ceilf(log2f(nrm * 4.0f));
        if (s < 0) s = 0;
    }
    float sc = exp2f((float)(-s));
    float B[9], T[9];
#pragma unroll
    for (int i = 0; i < 9; i++) B[i] = A[i] * sc;
#pragma unroll
    for (int i = 0; i < 9; i++) {
        T[i] = B[i];
        E[i] = ((i == 0) | (i == 4) | (i == 8)) ? 1.0f + B[i] : B[i];
    }
#pragma unroll
    for (int j = 2; j <= 10; j++) {
        float Tn[9];
        mm3(T, B, Tn);
        float inv = 1.0f / (float)j;
#pragma unroll
        for (int i = 0; i < 9; i++) { Tn[i] *= inv; E[i] += Tn[i]; T[i] = Tn[i]; }
    }
    for (int q = 0; q < s; q++) {
        float S[9];
        mm3(E, E, S);
#pragma unroll
        for (int i = 0; i < 9; i++) E[i] = S[i];
    }
}

__global__ __launch_bounds__(256) void expm_assemble_kernel(
    const float* __restrict__ omega_t,  // (K, 9n)
    const float* __restrict__ trans_t,  // (K, 3n)
    float* __restrict__ omega_out,      // (9n, K)
    float* __restrict__ transf,         // (12n, K)
    float* __restrict__ rot,            // (9n, K)
    float* __restrict__ trans_out)      // (3n, K)
{
    const int n = blockIdx.x * 256 + threadIdx.x;
    const int p = blockIdx.y;

    float Am[9];
    const float* src = omega_t + (size_t)n * OMEGA_D + 9 * p;
#pragma unroll
    for (int j = 0; j < 9; j++) Am[j] = __ldg(src + j);

    float E[9];
    expm3(Am, E);

#pragma unroll
    for (int j = 0; j < 9; j++) {
        omega_out[(size_t)(9 * p + j) * KCOLS + n] = Am[j];
        rot[(size_t)(9 * p + j) * KCOLS + n]       = E[j];
        transf[(size_t)(12 * p + j) * KCOLS + n]   = E[j];
    }
    const float* tsrc = trans_t + (size_t)n * TRANZ_D + 3 * p;
#pragma unroll
    for (int c = 0; c < 3; c++) {
        float tv = __ldg(tsrc + c);
        trans_out[(size_t)(3 * p + c) * KCOLS + n]   = tv;
        transf[(size_t)(12 * p + 9 + c) * KCOLS + n] = tv;
    }
}

// ---------------------------------------------------------------------------
// kernel_launch
// ---------------------------------------------------------------------------
extern "C" void kernel_launch(void* const* d_in, const int* in_sizes, int n_in,
                              void* d_out, int out_size)
{
    const float* x = (const float*)d_in[0];
    const float* W[8];
    for (int i = 0; i < 8; i++) W[i] = (const float*)d_in[1 + i];

    const int wsz[8] = {2048 * 128, 2048 * 2048, 2048 * 2048, 1152 * 2048,
                        2048 * 128, 2048 * 2048, 2048 * 2048, 384 * 2048};
    size_t woff[8];
    size_t acc = 0;
    for (int i = 0; i < 8; i++) { woff[i] = acc; acc += wsz[i]; }

    float* out    = (float*)d_out;
    float* omega  = out;
    float* transf = omega  + (size_t)OMEGA_D  * KCOLS;
    float* rot    = transf + (size_t)TRANSF_D * KCOLS;
    float* trans  = rot    + (size_t)OMEGA_D  * KCOLS;

    __nv_bfloat16 *w_hi, *w_lo, *xt_hi, *xt_lo;
    __nv_bfloat16 *a_hi[2], *a_lo[2];
    float *omega_t, *trans_t;
    cudaGetSymbolAddress((void**)&w_hi, g_w_hi);
    cudaGetSymbolAddress((void**)&w_lo, g_w_lo);
    cudaGetSymbolAddress((void**)&xt_hi, g_xt_hi);
    cudaGetSymbolAddress((void**)&xt_lo, g_xt_lo);
    {
        __nv_bfloat16* p;
        cudaGetSymbolAddress((void**)&p, g_act_hi);
        a_hi[0] = p; a_hi[1] = p + (size_t)HIDDEN * KCOLS;
        cudaGetSymbolAddress((void**)&p, g_act_lo);
        a_lo[0] = p; a_lo[1] = p + (size_t)HIDDEN * KCOLS;
    }
    cudaGetSymbolAddress((void**)&omega_t, g_omega_t);
    cudaGetSymbolAddress((void**)&trans_t, g_trans_t);

    cudaFuncSetAttribute(gemm_hmma_kernel,
                         cudaFuncAttributeMaxDynamicSharedMemorySize, GEMM_SMEM);

    // 1) split weights + x (vectorized)
    for (int i = 0; i < 8; i++) {
        int n4 = wsz[i] / 4;
        split4_kernel<<<(n4 + 255) / 256, 256>>>(W[i], w_hi + woff[i],
                                                 w_lo + woff[i], n4);
    }
    split_xT_kernel<<<(KCOLS * LATENT) / 256, 256>>>(x, xt_hi, xt_lo);

    // 2) GEMM chains (activations transposed throughout)
    auto gemm = [&](int wi, const __nv_bfloat16* bh, const __nv_bfloat16* bl,
                    __nv_bfloat16* oh, __nv_bfloat16* ol, float* of,
                    int M, int Kd, int mode) {
        dim3 grid(KCOLS / BN, M / BM);
        gemm_hmma_kernel<<<grid, GT, GEMM_SMEM>>>(
            w_hi + woff[wi], w_lo + woff[wi], bh, bl, oh, ol, of, M, Kd, mode);
    };

    // omega branch
    gemm(0, xt_hi,   xt_lo,   a_hi[0], a_lo[0], nullptr, HIDDEN,  LATENT, 0);
    gemm(1, a_hi[0], a_lo[0], a_hi[1], a_lo[1], nullptr, HIDDEN,  HIDDEN, 0);
    gemm(2, a_hi[1], a_lo[1], a_hi[0], a_lo[0], nullptr, HIDDEN,  HIDDEN, 0);
    gemm(3, a_hi[0], a_lo[0], nullptr, nullptr, omega_t, OMEGA_D, HIDDEN, 1);
    // translation branch
    gemm(4, xt_hi,   xt_lo,   a_hi[0], a_lo[0], nullptr, HIDDEN,  LATENT, 0);
    gemm(5, a_hi[0], a_lo[0], a_hi[1], a_lo[1], nullptr, HIDDEN,  HIDDEN, 0);
    gemm(6, a_hi[1], a_lo[1], a_hi[0], a_lo[0], nullptr, HIDDEN,  HIDDEN, 0);
    gemm(7, a_hi[0], a_lo[0], nullptr, nullptr, trans_t, TRANZ_D, HIDDEN, 1);

    // 3) expm + assembly
    dim3 ge(KCOLS / 256, NPARTS);
    expm_assemble_kernel<<<ge, 256>>>(omega_t, trans_t, omega, transf, rot, trans);
}

// round 5
// speedup vs baseline: 2.4488x; 1.0212x over previous
#include <cuda_runtime.h>
#include <cuda_fp16.h>
#include <cstdint>

#define LATENT   128
#define HIDDEN   2048
#define NPARTS   128
#define KCOLS    2048
#define OMEGA_D  1152
#define TRANZ_D  384
#define TRANSF_D 1536

// ---------------------------------------------------------------------------
// Scratch (__device__ globals; allocation-guard-safe)
// ---------------------------------------------------------------------------
#define W_TOTAL (2048*128 + 2048*2048 + 2048*2048 + 1152*2048 + \
                 2048*128 + 2048*2048 + 2048*2048 + 384*2048)

__device__ __half g_w_hi[W_TOTAL];
__device__ __half g_w_lo[W_TOTAL];
__device__ __half g_act_hi[2][HIDDEN * KCOLS];
__device__ __half g_act_lo[2][HIDDEN * KCOLS];
__device__ __half g_xt_hi[KCOLS * LATENT];
__device__ __half g_xt_lo[KCOLS * LATENT];
__device__ float g_omega_t[(size_t)KCOLS * OMEGA_D];
__device__ float g_trans_part[3 * (size_t)KCOLS * TRANZ_D];

// ---------------------------------------------------------------------------
// PTX helpers (base ISA: ldmatrix / mma.sync / cp.async)
// ---------------------------------------------------------------------------
__device__ __forceinline__ uint32_t smem_u32(const void* p) {
    uint32_t a;
    asm("{ .reg .u64 t; cvta.to.shared.u64 t, %1; cvt.u32.u64 %0, t; }" : "=r"(a) : "l"(p));
    return a;
}
__device__ __forceinline__ void cp16(uint32_t s, const void* g) {
    asm volatile("cp.async.cg.shared.global [%0], [%1], 16;" :: "r"(s), "l"(g) : "memory");
}
#define CP_COMMIT() asm volatile("cp.async.commit_group;" ::: "memory")

__device__ __forceinline__ void ldsm_x4(uint32_t addr, uint32_t* r) {
    asm volatile("ldmatrix.sync.aligned.m8n8.x4.shared.b16 {%0,%1,%2,%3}, [%4];"
                 : "=r"(r[0]), "=r"(r[1]), "=r"(r[2]), "=r"(r[3]) : "r"(addr));
}
__device__ __forceinline__ void mma_f16(float* c, const uint32_t* a,
                                        uint32_t b0, uint32_t b1) {
    asm volatile(
        "mma.sync.aligned.m16n8k16.row.col.f32.f16.f16.f32 "
        "{%0,%1,%2,%3}, {%4,%5,%6,%7}, {%8,%9}, {%0,%1,%2,%3};"
        : "+f"(c[0]), "+f"(c[1]), "+f"(c[2]), "+f"(c[3])
        : "r"(a[0]), "r"(a[1]), "r"(a[2]), "r"(a[3]), "r"(b0), "r"(b1));
}

// ---------------------------------------------------------------------------
// Fused weight split: all 8 weights -> (hi, lo) fp16, one launch.
// Element order in g_w_hi/lo matches concatenated metadata order.
// ---------------------------------------------------------------------------
__global__ __launch_bounds__(256) void split_w_kernel(
    const float* __restrict__ w0, const float* __restrict__ w1,
    const float* __restrict__ w2, const float* __restrict__ w3,
    const float* __restrict__ w4, const float* __restrict__ w5,
    const float* __restrict__ w6, const float* __restrict__ w7,
    __half* __restrict__ hi, __half* __restrict__ lo)
{
    // float4 counts per segment
    const int cum[8] = {65536, 1114112, 2162688, 2752512,
                        2818048, 3866624, 4915200, 5111808};
    int idx = blockIdx.x * 256 + threadIdx.x;
    if (idx >= 5111808) return;
    const float* srcs[8] = {w0, w1, w2, w3, w4, w5, w6, w7};
    int s = 0;
#pragma unroll
    for (int i = 0; i < 7; i++) s += (idx >= cum[i]);
    int local = idx - (s ? cum[s - 1] : 0);
    float4 v = ((const float4*)srcs[s])[local];
    float f[4] = {v.x, v.y, v.z, v.w};
    __align__(8) __half h[4], l[4];
#pragma unroll
    for (int j = 0; j < 4; j++) {
        h[j] = __float2half(f[j]);
        l[j] = __float2half(f[j] - __half2float(h[j]));
    }
    ((uint2*)hi)[idx] = *(const uint2*)h;
    ((uint2*)lo)[idx] = *(const uint2*)l;
}

// x (LATENT, KCOLS) -> xt (KCOLS, LATENT), split fp16
__global__ __launch_bounds__(256) void split_xT_kernel(
    const float* __restrict__ x, __half* __restrict__ hi,
    __half* __restrict__ lo)
{
    int i = blockIdx.x * 256 + threadIdx.x;  // i = n*LATENT + f
    int f = i & (LATENT - 1);
    int n = i >> 7;
    float v = x[(size_t)f * KCOLS + n];
    __half h = __float2half(v);
    hi[i] = h;
    lo[i] = __float2half(v - __half2float(h));
}

// ---------------------------------------------------------------------------
// HMMA split-fp16 GEMM (3-MMA scheme: AhBh + AhBl + AlBh).
//   C[M, KCOLS] = A[M, Kd] @ Bt[KCOLS, Kd]^T, output TRANSPOSED [n][M].
//   mode 0: relu + hi/lo fp16 split;  mode 1: fp32 raw.
//   Split-K: blockIdx.z selects kt range [z*ktps, min(KT, (z+1)*ktps));
//   fp32 output offset by z*out_stride.
// CTA 128x128x32, 256 threads, warp tile 64x32, 3-stage cp.async.
// ---------------------------------------------------------------------------
#define BM 128
#define BN 128
#define BK 32
#define GT 256
#define PITCH 80
#define TILE_B (128 * PITCH)
#define STAGE_B (4 * TILE_B)
#define NSTAGE 3
#define GEMM_SMEM (NSTAGE * STAGE_B)   // 122880
#define OFF_AH 0
#define OFF_AL TILE_B
#define OFF_BH (2 * TILE_B)
#define OFF_BL (3 * TILE_B)

__device__ __forceinline__ void load_stage(
    const __half* __restrict__ Ah, const __half* __restrict__ Al,
    const __half* __restrict__ Bh, const __half* __restrict__ Bl,
    int Kd, int m0, int n0, int kk, uint32_t stage_sb, int tid)
{
    const int rr = tid >> 2;
    const int cb = (tid & 3) * 16;
#pragma unroll
    for (int h = 0; h < 2; h++) {
        const int row = rr + h * 64;
        const size_t goff = (size_t)row * Kd + kk;
        const uint32_t sa = stage_sb + row * PITCH + cb;
        cp16(sa + OFF_AH, (const char*)(Ah + (size_t)m0 * Kd + goff) + cb);
        cp16(sa + OFF_AL, (const char*)(Al + (size_t)m0 * Kd + goff) + cb);
        cp16(sa + OFF_BH, (const char*)(Bh + (size_t)n0 * Kd + goff) + cb);
        cp16(sa + OFF_BL, (const char*)(Bl + (size_t)n0 * Kd + goff) + cb);
    }
}

__global__ __launch_bounds__(GT, 1) void gemm_hmma_kernel(
    const __half* __restrict__ A_hi, const __half* __restrict__ A_lo,
    const __half* __restrict__ B_hi, const __half* __restrict__ B_lo,
    __half* __restrict__ out_hi, __half* __restrict__ out_lo,
    float* __restrict__ out_f32, int M, int Kd, int mode,
    int ktps, size_t out_stride)
{
    extern __shared__ __align__(128) char smem[];
    const uint32_t sb = smem_u32(smem);
    const int tid = threadIdx.x;
    const int lane = tid & 31;
    const int wid = tid >> 5;
    const int warp_m0 = (wid & 1) * 64;
    const int warp_n0 = (wid >> 1) * 32;
    const int m0 = blockIdx.y * BM;
    const int n0 = blockIdx.x * BN;
    const int KT = Kd / BK;
    const int ktb = blockIdx.z * ktps;
    const int L = min(KT - ktb, ktps);       // local kt count
    out_f32 += (size_t)blockIdx.z * out_stride;

    const int a_row = (lane & 7) + ((lane >> 3) & 1) * 8;
    const int a_kb  = (lane >> 4) * 16;
    const int b_row = (lane & 7) + (lane >> 4) * 8;
    const int b_kb  = ((lane >> 3) & 1) * 16;

    float acc[4][4][4];
#pragma unroll
    for (int mt = 0; mt < 4; mt++)
#pragma unroll
        for (int nt = 0; nt < 4; nt++)
#pragma unroll
            for (int i = 0; i < 4; i++) acc[mt][nt][i] = 0.0f;

    load_stage(A_hi, A_lo, B_hi, B_lo, Kd, m0, n0, ktb * BK, sb, tid);
    CP_COMMIT();
    load_stage(A_hi, A_lo, B_hi, B_lo, Kd, m0, n0, (ktb + 1) * BK, sb + STAGE_B, tid);
    CP_COMMIT();

    for (int kt = 0; kt < L; kt++) {
        asm volatile("cp.async.wait_group 1;" ::: "memory");
        __syncthreads();

        if (kt + 2 < L) {
            load_stage(A_hi, A_lo, B_hi, B_lo, Kd, m0, n0, (ktb + kt + 2) * BK,
                       sb + ((kt + 2) % NSTAGE) * STAGE_B, tid);
        }
        CP_COMMIT();

        const uint32_t st = sb + (kt % NSTAGE) * STAGE_B;
#pragma unroll
        for (int ks = 0; ks < 2; ks++) {
            const int kb = ks * 32;
            uint32_t ah[4][4], al[4][4], bh[2][4], bl[2][4];
#pragma unroll
            for (int mt = 0; mt < 4; mt++) {
                uint32_t ra = st + (warp_m0 + mt * 16 + a_row) * PITCH + kb + a_kb;
                ldsm_x4(ra + OFF_AH, ah[mt]);
                ldsm_x4(ra + OFF_AL, al[mt]);
            }
#pragma unroll
            for (int g = 0; g < 2; g++) {
                uint32_t rb = st + (warp_n0 + g * 16 + b_row) * PITCH + kb + b_kb;
                ldsm_x4(rb + OFF_BH, bh[g]);
                ldsm_x4(rb + OFF_BL, bl[g]);
            }
#pragma unroll
            for (int mt = 0; mt < 4; mt++)
#pragma unroll
                for (int nt = 0; nt < 4; nt++) {
                    const int g = nt >> 1, p = (nt & 1) * 2;
                    mma_f16(acc[mt][nt], ah[mt], bh[g][p], bh[g][p + 1]);
                    mma_f16(acc[mt][nt], ah[mt], bl[g][p], bl[g][p + 1]);
                    mma_f16(acc[mt][nt], al[mt], bh[g][p], bh[g][p + 1]);
                }
        }
    }

    // ---------------- epilogue: transpose via SMEM ----------------
    __syncthreads();
    float* sC = (float*)smem;  // [128 n][132 m]
    const int crow = lane >> 2, ccol = (lane & 3) * 2;
#pragma unroll
    for (int mt = 0; mt < 4; mt++)
#pragma unroll
        for (int nt = 0; nt < 4; nt++) {
            const int m_ = warp_m0 + mt * 16 + crow;
            const int n_ = warp_n0 + nt * 8 + ccol;
            const float* c = acc[mt][nt];
            sC[(size_t)n_ * 132 + m_]           = c[0];
            sC[(size_t)(n_ + 1) * 132 + m_]     = c[1];
            sC[(size_t)n_ * 132 + m_ + 8]       = c[2];
            sC[(size_t)(n_ + 1) * 132 + m_ + 8] = c[3];
        }
    __syncthreads();

    const int r  = tid >> 1;
    const int mh = (tid & 1) * 64;
    const size_t base = (size_t)(n0 + r) * M + m0 + mh;
    const float* srow = &sC[(size_t)r * 132 + mh];
    if (mode == 0) {
#pragma unroll
        for (int j0 = 0; j0 < 64; j0 += 8) {
            __align__(16) __half h8[8], l8[8];
#pragma unroll
            for (int j = 0; j < 8; j++) {
                float v = fmaxf(srow[j0 + j], 0.0f);
                __half h = __float2half(v);
                h8[j] = h;
                l8[j] = __float2half(v - __half2float(h));
            }
            *(uint4*)(out_hi + base + j0) = *(const uint4*)h8;
            *(uint4*)(out_lo + base + j0) = *(const uint4*)l8;
        }
    } else {
#pragma unroll
        for (int j0 = 0; j0 < 64; j0 += 4) {
            float4 v;
            v.x = srow[j0 + 0]; v.y = srow[j0 + 1];
            v.z = srow[j0 + 2]; v.w = srow[j0 + 3];
            *(float4*)(out_f32 + base + j0) = v;
        }
    }
}

// ---------------------------------------------------------------------------
// expm (3x3) + output assembly; sums 3 split-K partials for translations.
// ---------------------------------------------------------------------------
__device__ __forceinline__ void mm3(const float* X, const float* Y, float* Z) {
#pragma unroll
    for (int r = 0; r < 3; r++)
#pragma unroll
        for (int c = 0; c < 3; c++)
            Z[3 * r + c] = fmaf(X[3 * r + 0], Y[c],
                           fmaf(X[3 * r + 1], Y[3 + c], X[3 * r + 2] * Y[6 + c]));
}

__device__ void expm3(const float* A, float* E) {
    float n0 = fabsf(A[0]) + fabsf(A[1]) + fabsf(A[2]);
    float n1 = fabsf(A[3]) + fabsf(A[4]) + fabsf(A[5]);
    float n2 = fabsf(A[6]) + fabsf(A[7]) + fabsf(A[8]);
    float nrm = fmaxf(n0, fmaxf(n1, n2));
    int s = 0;
    if (nrm > 0.25f) {
        s = (int)ceilf(log2f(nrm * 4.0f));
        if (s < 0) s = 0;
    }
    float sc = exp2f((float)(-s));
    float B[9], T[9];
#pragma unroll
    for (int i = 0; i < 9; i++) B[i] = A[i] * sc;
#pragma unroll
    for (int i = 0; i < 9; i++) {
        T[i] = B[i];
        E[i] = ((i == 0) | (i == 4) | (i == 8)) ? 1.0f + B[i] : B[i];
    }
#pragma unroll
    for (int j = 2; j <= 10; j++) {
        float Tn[9];
        mm3(T, B, Tn);
        float inv = 1.0f / (float)j;
#pragma unroll
        for (int i = 0; i < 9; i++) { Tn[i] *= inv; E[i] += Tn[i]; T[i] = Tn[i]; }
    }
    for (int q = 0; q < s; q++) {
        float S[9];
        mm3(E, E, S);
#pragma unroll
        for (int i = 0; i < 9; i++) E[i] = S[i];
    }
}

__global__ __launch_bounds__(256) void expm_assemble_kernel(
    const float* __restrict__ omega_t,    // (K, 9n)
    const float* __restrict__ trans_part, // 3 x (K, 3n) split-K partials
    float* __restrict__ omega_out,        // (9n, K)
    float* __restrict__ transf,           // (12n, K)
    float* __restrict__ rot,              // (9n, K)
    float* __restrict__ trans_out)        // (3n, K)
{
    const int n = blockIdx.x * 256 + threadIdx.x;
    const int p = blockIdx.y;
    const size_t S = (size_t)KCOLS * TRANZ_D;

    float Am[9];
    const float* src = omega_t + (size_t)n * OMEGA_D + 9 * p;
#pragma unroll
    for (int j = 0; j < 9; j++) Am[j] = __ldg(src + j);

    float E[9];
    expm3(Am, E);

#pragma unroll
    for (int j = 0; j < 9; j++) {
        omega_out[(size_t)(9 * p + j) * KCOLS + n] = Am[j];
        rot[(size_t)(9 * p + j) * KCOLS + n]       = E[j];
        transf[(size_t)(12 * p + j) * KCOLS + n]   = E[j];
    }
    const size_t tbase = (size_t)n * TRANZ_D + 3 * p;
#pragma unroll
    for (int c = 0; c < 3; c++) {
        float tv = __ldg(trans_part + tbase + c)
                 + __ldg(trans_part + S + tbase + c)
                 + __ldg(trans_part + 2 * S + tbase + c);
        trans_out[(size_t)(3 * p + c) * KCOLS + n]   = tv;
        transf[(size_t)(12 * p + 9 + c) * KCOLS + n] = tv;
    }
}

// ---------------------------------------------------------------------------
// kernel_launch
// ---------------------------------------------------------------------------
extern "C" void kernel_launch(void* const* d_in, const int* in_sizes, int n_in,
                              void* d_out, int out_size)
{
    const float* x = (const float*)d_in[0];
    const float* W[8];
    for (int i = 0; i < 8; i++) W[i] = (const float*)d_in[1 + i];

    const int wsz[8] = {2048 * 128, 2048 * 2048, 2048 * 2048, 1152 * 2048,
                        2048 * 128, 2048 * 2048, 2048 * 2048, 384 * 2048};
    size_t woff[8];
    size_t acc = 0;
    for (int i = 0; i < 8; i++) { woff[i] = acc; acc += wsz[i]; }

    float* out    = (float*)d_out;
    float* omega  = out;
    float* transf = omega  + (size_t)OMEGA_D  * KCOLS;
    float* rot    = transf + (size_t)TRANSF_D * KCOLS;
    float* trans  = rot    + (size_t)OMEGA_D  * KCOLS;

    __half *w_hi, *w_lo, *xt_hi, *xt_lo;
    __half *a_hi[2], *a_lo[2];
    float *omega_t, *trans_part;
    cudaGetSymbolAddress((void**)&w_hi, g_w_hi);
    cudaGetSymbolAddress((void**)&w_lo, g_w_lo);
    cudaGetSymbolAddress((void**)&xt_hi, g_xt_hi);
    cudaGetSymbolAddress((void**)&xt_lo, g_xt_lo);
    {
        __half* p;
        cudaGetSymbolAddress((void**)&p, g_act_hi);
        a_hi[0] = p; a_hi[1] = p + (size_t)HIDDEN * KCOLS;
        cudaGetSymbolAddress((void**)&p, g_act_lo);
        a_lo[0] = p; a_lo[1] = p + (size_t)HIDDEN * KCOLS;
    }
    cudaGetSymbolAddress((void**)&omega_t, g_omega_t);
    cudaGetSymbolAddress((void**)&trans_part, g_trans_part);

    cudaFuncSetAttribute(gemm_hmma_kernel,
                         cudaFuncAttributeMaxDynamicSharedMemorySize, GEMM_SMEM);

    // 1) fused weight split (launch 1) + xT split (launch 2)
    split_w_kernel<<<(5111808 + 255) / 256, 256>>>(
        W[0], W[1], W[2], W[3], W[4], W[5], W[6], W[7], w_hi, w_lo);
    split_xT_kernel<<<(KCOLS * LATENT) / 256, 256>>>(x, xt_hi, xt_lo);

    // 2) GEMM chains
    auto gemm = [&](int wi, const __half* bh, const __half* bl,
                    __half* oh, __half* ol, float* of,
                    int M, int Kd, int mode, int zsplits, size_t ostride) {
        int KT = Kd / BK;
        int ktps = (KT + zsplits - 1) / zsplits;
        dim3 grid(KCOLS / BN, M / BM, zsplits);
        gemm_hmma_kernel<<<grid, GT, GEMM_SMEM>>>(
            w_hi + woff[wi], w_lo + woff[wi], bh, bl, oh, ol, of,
            M, Kd, mode, ktps, ostride);
    };

    // omega branch (launches 3..6; launch #6 = layer3 big GEMM for ncu)
    gemm(0, xt_hi,   xt_lo,   a_hi[0], a_lo[0], nullptr, HIDDEN,  LATENT, 0, 1, 0);
    gemm(1, a_hi[0], a_lo[0], a_hi[1], a_lo[1], nullptr, HIDDEN,  HIDDEN, 0, 1, 0);
    gemm(2, a_hi[1], a_lo[1], a_hi[0], a_lo[0], nullptr, HIDDEN,  HIDDEN, 0, 1, 0);
    gemm(3, a_hi[0], a_lo[0], nullptr, nullptr, omega_t, OMEGA_D, HIDDEN, 1, 1, 0);
    // translation branch; final layer split-K x3
    gemm(4, xt_hi,   xt_lo,   a_hi[0], a_lo[0], nullptr, HIDDEN,  LATENT, 0, 1, 0);
    gemm(5, a_hi[0], a_lo[0], a_hi[1], a_lo[1], nullptr, HIDDEN,  HIDDEN, 0, 1, 0);
    gemm(6, a_hi[1], a_lo[1], a_hi[0], a_lo[0], nullptr, HIDDEN,  HIDDEN, 0, 1, 0);
    gemm(7, a_hi[0], a_lo[0], nullptr, nullptr, trans_part, TRANZ_D, HIDDEN, 1,
         3, (size_t)KCOLS * TRANZ_D);

    // 3) expm + assembly (sums split-K partials deterministically)
    dim3 ge(KCOLS / 256, NPARTS);
    expm_assemble_kernel<<<ge, 256>>>(omega_t, trans_part, omega, transf, rot, trans);
}